// round 12
// baseline (speedup 1.0000x reference)
#include <cuda_runtime.h>
#include <cuda_bf16.h>
#include <cstdint>

#define NB  16
#define NC  512
#define NHW 4096
#define NIP 10

// ---------------- scratch (static device globals; no allocations) ----------------
__device__ __align__(16) __nv_bfloat16 g_xh[NB*NC*NHW];    // bf16 copy of x (64MB)
__device__ __align__(16) __nv_bfloat16 g_Wsh[NB*NC*NC];    // Gram bf16 (8MB)
__device__ float g_v  [NB*NC];        // v after 10 power iterations
__device__ float g_u  [NB*NHW];       // unnormalized u = X^T v
__device__ float g_upar[NB*16*NHW];   // c-chunk partials of u (4MB)
__device__ float g_uinv [NB];         // 1/||u||

// ================= PTX helpers =================
__device__ __forceinline__ uint32_t smem_u32(const void* p) {
    uint32_t a;
    asm("{ .reg .u64 t; cvta.to.shared.u64 t, %1; cvt.u32.u64 %0, t; }" : "=r"(a) : "l"(p));
    return a;
}
__device__ __forceinline__ void cp16(uint32_t dst, const void* gsrc) {
    asm volatile("cp.async.cg.shared.global [%0], [%1], 16;"
                 :: "r"(dst), "l"(__cvta_generic_to_global(gsrc)) : "memory");
}
#define CP_COMMIT() asm volatile("cp.async.commit_group;" ::: "memory")

__device__ __forceinline__ void ldsm4(uint32_t* r, uint32_t addr) {
    asm volatile("ldmatrix.sync.aligned.m8n8.x4.shared.b16 {%0,%1,%2,%3}, [%4];"
        : "=r"(r[0]), "=r"(r[1]), "=r"(r[2]), "=r"(r[3]) : "r"(addr));
}
__device__ __forceinline__ void mma16816(float* d, const uint32_t* a, uint32_t b0, uint32_t b1) {
    asm volatile("mma.sync.aligned.m16n8k16.row.col.f32.bf16.bf16.f32 "
        "{%0,%1,%2,%3}, {%4,%5,%6,%7}, {%8,%9}, {%0,%1,%2,%3};"
        : "+f"(d[0]), "+f"(d[1]), "+f"(d[2]), "+f"(d[3])
        : "r"(a[0]), "r"(a[1]), "r"(a[2]), "r"(a[3]), "r"(b0), "r"(b1));
}
__device__ __forceinline__ float bflo(uint32_t p) { return __uint_as_float(p << 16); }
__device__ __forceinline__ float bfhi(uint32_t p) { return __uint_as_float(p & 0xffff0000u); }

// =====================================================================
// Kernels 0a/0b: convert x (f32) -> g_xh (bf16), split so gram is launch #4.
// =====================================================================
__global__ __launch_bounds__(256)
void conv_kernel(const float* __restrict__ x, int base) {
    const size_t i = (size_t)base + (size_t)blockIdx.x * 256 + threadIdx.x;  // float4 idx
    const float4 v = ((const float4*)x)[i];
    __nv_bfloat162 lo = __floats2bfloat162_rn(v.x, v.y);
    __nv_bfloat162 hi = __floats2bfloat162_rn(v.z, v.w);
    union { struct { __nv_bfloat162 a, b; } h; uint2 u; } cv;
    cv.h.a = lo; cv.h.b = hi;
    ((uint2*)g_xh)[i] = cv.u;
}

// Kernel 0c: trivial prep (slot filler; overwritten later by u_reduce).
__global__ void prep_kernel() {
    if (threadIdx.x < NB) g_uinv[threadIdx.x] = 0.f;
}

// =====================================================================
// Kernel 1: Gram via bf16 mma.sync. CTA tile 64x64, NO split-K.
// 36 lower-tri tiles x 16 batches = 576 CTAs -> 2 nearly-full waves
// (vs 3 waves with 16% tail at R11's 640).
// 256 threads = 8 warps mapped 2m x 2n x 2ks: warps (wid>>2)=0/1 own the
// low/high 32-K halves of each BK=64 chunk; partials summed in epilogue.
// Per-warp per-chunk profile (8 ldsm4 + 16 MMA, 1 barrier) == R11's.
// 4-stage cp.async pipeline, prefetch distance +2, one barrier per chunk.
// Rows 144B (verified R7). Writes bf16 Wsh directly (combine deleted);
// off-diag tiles also write their transpose.
// =====================================================================
#define BK 64
#define RSTR 144                      // bytes per 64-elem bf16 row (128 + 16 pad)
#define T_BYTES (64 * RSTR)           // 9216 per operand tile
#define STAGE_BYTES (2 * T_BYTES)     // 18432
#define GRAM_SMEM (4 * STAGE_BYTES)   // 73728 >= epilogue 2*64*65*4 (33280)

__global__ __launch_bounds__(256, 2)
void gram_mma(void) {
    extern __shared__ char ds[];
    const uint32_t sb = smem_u32(ds);
    const int tid = threadIdx.x;
    const int wid = tid >> 5, lane = tid & 31;

    const int b = blockIdx.y;
    int ti = 0, r = blockIdx.x;              // lower-tri: row ti has ti+1 tiles
    while (r >= ti + 1) { r -= ti + 1; ti++; }
    const int tj = r;                        // tj <= ti
    const int i0 = ti * 64, j0 = tj * 64;
    const bool diag = (ti == tj);

    const __nv_bfloat16* __restrict__ Xb = g_xh + (size_t)b * NC * NHW;
    __nv_bfloat16* __restrict__ Wh = g_Wsh + (size_t)b * NC * NC;

    // loader: per operand 64 rows x 8 x 16B = 512 cp16 -> 2 per thread
    const int lr0 = tid >> 3;                // 0..31
    const int lq0 = tid & 7;                 // 16B col 0..7

    auto load_chunk = [&](int c) {
        const uint32_t stg = sb + (uint32_t)(c & 3) * STAGE_BYTES;
        const __nv_bfloat16* gA = Xb + (size_t)i0 * NHW + c * BK;
        cp16(stg + lr0 * RSTR + lq0 * 16,        gA + (size_t)lr0 * NHW + lq0 * 8);
        cp16(stg + (lr0 + 32) * RSTR + lq0 * 16, gA + (size_t)(lr0 + 32) * NHW + lq0 * 8);
        if (!diag) {
            const uint32_t bbs = stg + T_BYTES;
            const __nv_bfloat16* gB = Xb + (size_t)j0 * NHW + c * BK;
            cp16(bbs + lr0 * RSTR + lq0 * 16,        gB + (size_t)lr0 * NHW + lq0 * 8);
            cp16(bbs + (lr0 + 32) * RSTR + lq0 * 16, gB + (size_t)(lr0 + 32) * NHW + lq0 * 8);
        }
        CP_COMMIT();
    };

    load_chunk(0); load_chunk(1);

    // per-lane ldmatrix address offsets (bytes) — verified R5/R7
    const uint32_t aoff = (uint32_t)((lane & 15) * RSTR + (lane >> 4) * 16);
    const uint32_t boff = (uint32_t)(((lane & 7) | (((lane >> 4) & 1) << 3)) * RSTR
                                     + ((lane >> 3) & 1) * 16);
    const uint32_t wmB = (uint32_t)((wid & 1) * 32) * RSTR;        // warp m0
    const uint32_t wnB = (uint32_t)(((wid >> 1) & 1) * 32) * RSTR; // warp n0
    const uint32_t wkB = (uint32_t)(wid >> 2) * 64u;               // warp K-half (bytes)

    float acc[2][4][4];
    #pragma unroll
    for (int mt = 0; mt < 2; mt++)
        #pragma unroll
        for (int nt = 0; nt < 4; nt++)
            #pragma unroll
            for (int q = 0; q < 4; q++) acc[mt][nt][q] = 0.f;

    for (int c = 0; c < 64; c++) {
        if (c < 63) asm volatile("cp.async.wait_group 1;" ::: "memory");
        else        asm volatile("cp.async.wait_group 0;" ::: "memory");
        __syncthreads();     // chunk c resident; stage (c+2)%4 reads (chunk c-2) done

        if (c + 2 < 64) load_chunk(c + 2);

        const uint32_t stg = sb + (uint32_t)(c & 3) * STAGE_BYTES;
        const uint32_t bbs = diag ? stg : (stg + T_BYTES);

        #pragma unroll
        for (int ks = 0; ks < 2; ks++) {
            const uint32_t koff = wkB + (uint32_t)(ks * 32);
            uint32_t af[2][4], bf[2][4];
            #pragma unroll
            for (int mt = 0; mt < 2; mt++)
                ldsm4(af[mt], stg + wmB + (uint32_t)(mt * 16 * RSTR) + koff + aoff);
            #pragma unroll
            for (int nh = 0; nh < 2; nh++)
                ldsm4(bf[nh], bbs + wnB + (uint32_t)(nh * 16 * RSTR) + koff + boff);
            #pragma unroll
            for (int mt = 0; mt < 2; mt++)
                #pragma unroll
                for (int nt = 0; nt < 4; nt++)
                    mma16816(acc[mt][nt], af[mt], bf[nt >> 1][2 * (nt & 1)],
                             bf[nt >> 1][2 * (nt & 1) + 1]);
        }
    }
    __syncthreads();   // all MMA reads done before smem reuse

    // ---- epilogue: two 64x64 f32 buffers (stride 65), one per ks-group ----
    float* st = (float*)ds;
    float* mybuf = st + (wid >> 2) * (64 * 65);
    {
        const int gid = lane >> 2, tig = lane & 3;
        const int wm0 = (wid & 1) * 32, wn0 = ((wid >> 1) & 1) * 32;
        #pragma unroll
        for (int mt = 0; mt < 2; mt++)
            #pragma unroll
            for (int nt = 0; nt < 4; nt++) {
                const int m = wm0 + mt * 16 + gid;
                const int n = wn0 + nt * 8 + tig * 2;
                mybuf[m * 65 + n]           = acc[mt][nt][0];
                mybuf[m * 65 + n + 1]       = acc[mt][nt][1];
                mybuf[(m + 8) * 65 + n]     = acc[mt][nt][2];
                mybuf[(m + 8) * 65 + n + 1] = acc[mt][nt][3];
            }
    }
    __syncthreads();

    float* b0 = st;
    float* b1 = st + 64 * 65;
    // direct block (i0, j0): 64 x 64, bf16, uint2 = 4 cols per thread-iter
    #pragma unroll
    for (int it = 0; it < 4; it++) {
        const int e = it * 256 + tid;        // 1024 uint2
        const int row = e >> 4, c4 = e & 15;
        const int n = c4 * 4;
        const float f0 = b0[row * 65 + n]     + b1[row * 65 + n];
        const float f1 = b0[row * 65 + n + 1] + b1[row * 65 + n + 1];
        const float f2 = b0[row * 65 + n + 2] + b1[row * 65 + n + 2];
        const float f3 = b0[row * 65 + n + 3] + b1[row * 65 + n + 3];
        union { struct { __nv_bfloat162 a, b; } h; uint2 u; } cv;
        cv.h.a = __floats2bfloat162_rn(f0, f1);
        cv.h.b = __floats2bfloat162_rn(f2, f3);
        *(uint2*)&Wh[(size_t)(i0 + row) * NC + j0 + n] = cv.u;
    }
    // transposed block (j0, i0): 64 x 64
    if (!diag) {
        #pragma unroll
        for (int it = 0; it < 4; it++) {
            const int e = it * 256 + tid;
            const int n = e >> 4, m4 = e & 15;
            const int m = m4 * 4;
            const float f0 = b0[m * 65 + n]       + b1[m * 65 + n];
            const float f1 = b0[(m + 1) * 65 + n] + b1[(m + 1) * 65 + n];
            const float f2 = b0[(m + 2) * 65 + n] + b1[(m + 2) * 65 + n];
            const float f3 = b0[(m + 3) * 65 + n] + b1[(m + 3) * 65 + n];
            union { struct { __nv_bfloat162 a, b; } h; uint2 u; } cv;
            cv.h.a = __floats2bfloat162_rn(f0, f1);
            cv.h.b = __floats2bfloat162_rn(f2, f3);
            *(uint2*)&Wh[(size_t)(j0 + n) * NC + i0 + m] = cv.u;
        }
    }
}

// =====================================================================
// Kernel 2: 10 power iterations on bf16 Ws. One block/batch, 1024 threads.
// 8-way d-split, each thread 4 consecutive c via uint2 (4 bf16).
// =====================================================================
__global__ __launch_bounds__(1024)
void power_kernel(const float* __restrict__ vin) {
    const int b = blockIdx.x, t = threadIdx.x;
    const int h = t >> 7;        // d-chunk 0..7 (64 d each)
    const int cg = t & 127;      // c-group: c = 4*cg
    __shared__ float vs[NC];
    __shared__ float part[8 * NC];
    __shared__ float red[16];
    __shared__ float tot;

    const __nv_bfloat16* __restrict__ Wh = g_Wsh + (size_t)b * NC * NC;
    if (t < NC) vs[t] = vin[b * NC + t];
    __syncthreads();

    const uint2* __restrict__ base = (const uint2*)(Wh + (size_t)(h * 64) * NC) + cg;

    for (int it = 0; it < NIP; it++) {
        float a0 = 0.f, a1 = 0.f, a2 = 0.f, a3 = 0.f;
        #pragma unroll 16
        for (int d = 0; d < 64; d++) {
            const uint2 p = base[(size_t)d * (NC / 4)];
            const float vv = vs[h * 64 + d];
            a0 += vv * bflo(p.x); a1 += vv * bfhi(p.x);
            a2 += vv * bflo(p.y); a3 += vv * bfhi(p.y);
        }
        *(float4*)&part[h * NC + cg * 4] = make_float4(a0, a1, a2, a3);
        __syncthreads();

        float nv = 0.f;
        if (t < NC) {
            #pragma unroll
            for (int hh = 0; hh < 8; hh++) nv += part[hh * NC + t];
            float s = nv * nv;
            #pragma unroll
            for (int o = 16; o > 0; o >>= 1)
                s += __shfl_xor_sync(0xffffffffu, s, o);
            if ((t & 31) == 0) red[t >> 5] = s;
        }
        __syncthreads();
        if (t == 0) {
            float x = 0.f;
            #pragma unroll
            for (int i = 0; i < 16; i++) x += red[i];
            tot = x;
        }
        __syncthreads();
        if (t < NC) vs[t] = nv * rsqrtf(tot);
        __syncthreads();
    }
    if (t < NC) g_v[b * NC + t] = vs[t];
}

// =====================================================================
// Kernel 3: u partials from bf16 X. grid (4, 16, 16), 256 thr,
// each thread 4 n via uint2 (4 bf16), 32 c.
// =====================================================================
__global__ __launch_bounds__(256)
void u_part_kernel() {
    const int b = blockIdx.z, ch = blockIdx.y;
    const int n0 = blockIdx.x * 1024 + threadIdx.x * 4;
    __shared__ float vsh[32];
    if (threadIdx.x < 32) vsh[threadIdx.x] = g_v[b * NC + ch * 32 + threadIdx.x];
    __syncthreads();

    const __nv_bfloat16* __restrict__ Xp = g_xh + (size_t)b * NC * NHW + (size_t)(ch * 32) * NHW;
    float a0 = 0.f, a1 = 0.f, a2 = 0.f, a3 = 0.f;
    #pragma unroll
    for (int cc = 0; cc < 32; cc++) {
        const uint2 p = *(const uint2*)&Xp[(size_t)cc * NHW + n0];
        const float vv = vsh[cc];
        a0 += vv * bflo(p.x); a1 += vv * bfhi(p.x);
        a2 += vv * bflo(p.y); a3 += vv * bfhi(p.y);
    }
    *(float4*)&g_upar[(size_t)(b * 16 + ch) * NHW + n0] = make_float4(a0, a1, a2, a3);
}

// =====================================================================
// Kernel 4: reduce c-chunk partials -> g_u, compute 1/||u||. grid 16, 512 thr.
// =====================================================================
__global__ __launch_bounds__(512)
void u_reduce_kernel() {
    const int b = blockIdx.x, t = threadIdx.x;
    __shared__ float red[16];
    float sq = 0.f;
    #pragma unroll
    for (int j = 0; j < 8; j++) {
        const int n = j * 512 + t;
        float s = 0.f;
        #pragma unroll
        for (int ch = 0; ch < 16; ch++)
            s += g_upar[(size_t)(b * 16 + ch) * NHW + n];
        g_u[b * NHW + n] = s;
        sq += s * s;
    }
    #pragma unroll
    for (int o = 16; o > 0; o >>= 1)
        sq += __shfl_xor_sync(0xffffffffu, sq, o);
    if ((t & 31) == 0) red[t >> 5] = sq;
    __syncthreads();
    if (t == 0) {
        float x = 0.f;
        #pragma unroll
        for (int i = 0; i < 16; i++) x += red[i];
        g_uinv[b] = rsqrtf(x);
    }
}

// =====================================================================
// Kernel 5: out = x + (v * 1/||u||) outer u. float4 streaming (f32 x).
// =====================================================================
__global__ __launch_bounds__(256)
void final_kernel(const float* __restrict__ x, float* __restrict__ out) {
    const size_t i = (size_t)blockIdx.x * 256 + threadIdx.x;   // float4 idx
    const size_t e = i * 4;
    const int b   = (int)(e >> 21);                 // NC*NHW = 2^21
    const int rem = (int)(e & ((1u << 21) - 1));
    const int c   = rem >> 12;                      // NHW = 2^12
    const int n   = rem & (NHW - 1);
    const float vc = g_v[b * NC + c] * g_uinv[b];
    const float4 u4 = *(const float4*)&g_u[b * NHW + n];
    const float4 xv = *(const float4*)&x[e];
    float4 o;
    o.x = xv.x + vc * u4.x;
    o.y = xv.y + vc * u4.y;
    o.z = xv.z + vc * u4.z;
    o.w = xv.w + vc * u4.w;
    *(float4*)&out[e] = o;
}

// =====================================================================
extern "C" void kernel_launch(void* const* d_in, const int* in_sizes, int n_in,
                              void* d_out, int out_size) {
    const float* x  = (const float*)d_in[0];
    const float* v0 = (const float*)d_in[1];
    float* out = (float*)d_out;

    cudaFuncSetAttribute(gram_mma, cudaFuncAttributeMaxDynamicSharedMemorySize, GRAM_SMEM);

    conv_kernel<<<16384, 256>>>(x, 0);         // launch 1
    conv_kernel<<<16384, 256>>>(x, 16384*256); // launch 2
    prep_kernel<<<1, 32>>>();                  // launch 3 (slot filler)
    gram_mma<<<dim3(36, NB), 256, GRAM_SMEM>>>();   // launch 4 <- ncu capture slot
    power_kernel<<<NB, 1024>>>(v0);
    u_part_kernel<<<dim3(4, 16, NB), 256>>>();
    u_reduce_kernel<<<NB, 512>>>();
    final_kernel<<<32768, 256>>>(x, out);
}

// round 13
// speedup vs baseline: 1.2087x; 1.2087x over previous
#include <cuda_runtime.h>
#include <cuda_bf16.h>
#include <cstdint>

#define NB  16
#define NC  512
#define NHW 4096
#define NIP 10

// ---------------- scratch (static device globals; no allocations) ----------------
__device__ __align__(16) __nv_bfloat16 g_xh[NB*NC*NHW];    // bf16 copy of x (64MB)
__device__ float g_WsA[NB*NC*NC];                          // split-K half 0 (16MB)
__device__ float g_WsB[NB*NC*NC];                          // split-K half 1 (16MB)
__device__ __align__(16) __nv_bfloat16 g_Wsh[NB*NC*NC];    // Gram bf16 (8MB)
__device__ float g_v  [NB*NC];        // v after 10 power iterations
__device__ float g_u  [NB*NHW];       // unnormalized u = X^T v
__device__ float g_upar[NB*16*NHW];   // c-chunk partials of u (4MB)
__device__ float g_uinv [NB];         // 1/||u||

// ================= PTX helpers =================
__device__ __forceinline__ uint32_t smem_u32(const void* p) {
    uint32_t a;
    asm("{ .reg .u64 t; cvta.to.shared.u64 t, %1; cvt.u32.u64 %0, t; }" : "=r"(a) : "l"(p));
    return a;
}
__device__ __forceinline__ void cp16(uint32_t dst, const void* gsrc) {
    asm volatile("cp.async.cg.shared.global [%0], [%1], 16;"
                 :: "r"(dst), "l"(__cvta_generic_to_global(gsrc)) : "memory");
}
#define CP_COMMIT() asm volatile("cp.async.commit_group;" ::: "memory")

__device__ __forceinline__ void ldsm4(uint32_t* r, uint32_t addr) {
    asm volatile("ldmatrix.sync.aligned.m8n8.x4.shared.b16 {%0,%1,%2,%3}, [%4];"
        : "=r"(r[0]), "=r"(r[1]), "=r"(r[2]), "=r"(r[3]) : "r"(addr));
}
__device__ __forceinline__ void mma16816(float* d, const uint32_t* a, uint32_t b0, uint32_t b1) {
    asm volatile("mma.sync.aligned.m16n8k16.row.col.f32.bf16.bf16.f32 "
        "{%0,%1,%2,%3}, {%4,%5,%6,%7}, {%8,%9}, {%0,%1,%2,%3};"
        : "+f"(d[0]), "+f"(d[1]), "+f"(d[2]), "+f"(d[3])
        : "r"(a[0]), "r"(a[1]), "r"(a[2]), "r"(a[3]), "r"(b0), "r"(b1));
}
__device__ __forceinline__ float bflo(uint32_t p) { return __uint_as_float(p << 16); }
__device__ __forceinline__ float bfhi(uint32_t p) { return __uint_as_float(p & 0xffff0000u); }

// =====================================================================
// Kernels 0a/0b: convert x (f32) -> g_xh (bf16), split so gram is launch #4.
// =====================================================================
__global__ __launch_bounds__(256)
void conv_kernel(const float* __restrict__ x, int base) {
    const size_t i = (size_t)base + (size_t)blockIdx.x * 256 + threadIdx.x;  // float4 idx
    const float4 v = ((const float4*)x)[i];
    __nv_bfloat162 lo = __floats2bfloat162_rn(v.x, v.y);
    __nv_bfloat162 hi = __floats2bfloat162_rn(v.z, v.w);
    union { struct { __nv_bfloat162 a, b; } h; uint2 u; } cv;
    cv.h.a = lo; cv.h.b = hi;
    ((uint2*)g_xh)[i] = cv.u;
}

// Kernel 0c: trivial prep (slot filler; overwritten later by u_reduce).
__global__ void prep_kernel() {
    if (threadIdx.x < NB) g_uinv[threadIdx.x] = 0.f;
}

// =====================================================================
// Kernel 1: Gram via bf16 mma.sync. CTA tile 64x128, 256 threads = 8 warps
// (2m x 4n of 32x32 warp tiles). __launch_bounds__(256,3): 3 CTAs/SM
// (24 warps) to hide ldsm/MMA latency — the single change vs R11.
// Symmetric decomposition (mi in 0..7, nj in 0..3): tiles with mi >= 2nj.
// Straddle tiles alias A into B smem. Split-K=2, BK=32, 4-stage cp.async,
// prefetch +2, one barrier per chunk.
// =====================================================================
#define BK 32
#define A_BYTES (64 * 80)             // 5120
#define B_BYTES (128 * 80)            // 10240
#define STAGE_BYTES (A_BYTES + B_BYTES)  // 15360
#define GRAM_SMEM (4 * STAGE_BYTES)   // 61440 >= epilogue 64*129*4 (33024)

__global__ __launch_bounds__(256, 3)
void gram_mma(void) {
    extern __shared__ char ds[];
    const uint32_t sb = smem_u32(ds);
    const int tid = threadIdx.x;
    const int wid = tid >> 5, lane = tid & 31;

    const int b = blockIdx.y;
    const int z = blockIdx.z;            // split-K half
    int nj = 0, r = blockIdx.x;
    while (r >= 8 - 2 * nj) { r -= 8 - 2 * nj; nj++; }
    const int mi = 2 * nj + r;
    const int i0 = mi * 64, j0 = nj * 128;
    const bool straddle = (mi == 2 * nj) || (mi == 2 * nj + 1);
    const bool dotrans  = (mi >= 2 * nj + 2);
    const int kbase = z * 2048;

    const __nv_bfloat16* __restrict__ Xb = g_xh + (size_t)b * NC * NHW;
    float* __restrict__ Wz = (z ? g_WsB : g_WsA) + (size_t)b * NC * NC;

    // loader: B = 2 cp16/thread (128 rows x 4 qcols), A = 1 cp16/thread (64 x 4)
    const int br0 = tid >> 2,          bq0 = tid & 3;
    const int br1 = (tid + 256) >> 2,  bq1 = tid & 3;
    const int arow = tid >> 2,         akq = tid & 3;

    auto load_chunk = [&](int c) {
        const uint32_t stg = sb + (uint32_t)(c & 3) * STAGE_BYTES;
        const uint32_t bbs = stg + A_BYTES;
        const __nv_bfloat16* gB = Xb + (size_t)j0 * NHW + kbase + c * BK;
        cp16(bbs + br0 * 80 + bq0 * 16, gB + (size_t)br0 * NHW + bq0 * 8);
        cp16(bbs + br1 * 80 + bq1 * 16, gB + (size_t)br1 * NHW + bq1 * 8);
        if (!straddle) {
            const __nv_bfloat16* gA = Xb + (size_t)i0 * NHW + kbase + c * BK;
            cp16(stg + arow * 80 + akq * 16, gA + (size_t)arow * NHW + akq * 8);
        }
        CP_COMMIT();
    };

    load_chunk(0); load_chunk(1);

    // per-lane ldmatrix address offsets (bytes) — verified R5/R6/R9/R10/R11
    const uint32_t aoff = (uint32_t)((lane & 15) * 80 + (lane >> 4) * 16);
    const uint32_t boff = (uint32_t)(((lane & 7) | (((lane >> 4) & 1) << 3)) * 80
                                     + ((lane >> 3) & 1) * 16);
    const uint32_t wmB = (uint32_t)((wid & 1) * 32) * 80;   // warp m0 byte off
    const uint32_t wnB = (uint32_t)((wid >> 1) * 32) * 80;  // warp n0 byte off
    const uint32_t astrad = (uint32_t)(mi & 1) * 5120u;     // A offset inside B tile

    float acc[2][4][4];
    #pragma unroll
    for (int mt = 0; mt < 2; mt++)
        #pragma unroll
        for (int nt = 0; nt < 4; nt++)
            #pragma unroll
            for (int q = 0; q < 4; q++) acc[mt][nt][q] = 0.f;

    for (int c = 0; c < 64; c++) {
        if (c < 63) asm volatile("cp.async.wait_group 1;" ::: "memory");
        else        asm volatile("cp.async.wait_group 0;" ::: "memory");
        __syncthreads();     // chunk c resident; stage (c+2)%4 reads (chunk c-2) done

        if (c + 2 < 64) load_chunk(c + 2);

        const uint32_t stg = sb + (uint32_t)(c & 3) * STAGE_BYTES;
        const uint32_t bbs = stg + A_BYTES;
        const uint32_t abs_ = straddle ? (bbs + astrad) : stg;

        #pragma unroll
        for (int ks = 0; ks < 2; ks++) {
            uint32_t af[2][4], bf[2][4];
            #pragma unroll
            for (int mt = 0; mt < 2; mt++)
                ldsm4(af[mt], abs_ + wmB + (uint32_t)(mt * 1280 + ks * 32) + aoff);
            #pragma unroll
            for (int nh = 0; nh < 2; nh++)
                ldsm4(bf[nh], bbs + wnB + (uint32_t)(nh * 1280 + ks * 32) + boff);
            #pragma unroll
            for (int mt = 0; mt < 2; mt++)
                #pragma unroll
                for (int nt = 0; nt < 4; nt++)
                    mma16816(acc[mt][nt], af[mt], bf[nt >> 1][2 * (nt & 1)],
                             bf[nt >> 1][2 * (nt & 1) + 1]);
        }
    }
    __syncthreads();   // all MMA reads done before smem reuse

    // ---- epilogue: stage 64x128 C in smem (stride 129 floats) ----
    float* st = (float*)ds;
    {
        const int gid = lane >> 2, tig = lane & 3;
        const int wm0 = (wid & 1) * 32, wn0 = (wid >> 1) * 32;
        #pragma unroll
        for (int mt = 0; mt < 2; mt++)
            #pragma unroll
            for (int nt = 0; nt < 4; nt++) {
                const int m = wm0 + mt * 16 + gid;
                const int n = wn0 + nt * 8 + tig * 2;
                st[m * 129 + n]           = acc[mt][nt][0];
                st[m * 129 + n + 1]       = acc[mt][nt][1];
                st[(m + 8) * 129 + n]     = acc[mt][nt][2];
                st[(m + 8) * 129 + n + 1] = acc[mt][nt][3];
            }
    }
    __syncthreads();

    // direct block (i0, j0): 64 x 128
    #pragma unroll
    for (int it = 0; it < 8; it++) {
        const int e = it * 256 + tid;        // 2048 float4
        const int row = e >> 5, c4 = e & 31;
        float4 w = make_float4(st[row * 129 + c4 * 4],     st[row * 129 + c4 * 4 + 1],
                               st[row * 129 + c4 * 4 + 2], st[row * 129 + c4 * 4 + 3]);
        *(float4*)&Wz[(size_t)(i0 + row) * NC + j0 + c4 * 4] = w;
    }
    // transposed block (j0, i0): 128 x 64 (only when fully below diagonal band)
    if (dotrans) {
        #pragma unroll
        for (int it = 0; it < 8; it++) {
            const int e = it * 256 + tid;    // 2048 float4
            const int n = e >> 4, m4 = e & 15;
            float4 w = make_float4(st[(m4 * 4)     * 129 + n], st[(m4 * 4 + 1) * 129 + n],
                                   st[(m4 * 4 + 2) * 129 + n], st[(m4 * 4 + 3) * 129 + n]);
            *(float4*)&Wz[(size_t)(j0 + n) * NC + i0 + m4 * 4] = w;
        }
    }
}

// =====================================================================
// Kernel 1b: combine split-K halves -> g_Wsh (bf16 only). Full-chip.
// =====================================================================
__global__ __launch_bounds__(256)
void combine_kernel() {
    const size_t i = (size_t)blockIdx.x * 256 + threadIdx.x;   // float4 idx (4M/4)
    const float4 a = ((const float4*)g_WsA)[i];
    const float4 b = ((const float4*)g_WsB)[i];
    union { struct { __nv_bfloat162 a, b; } h; uint2 u; } cv;
    cv.h.a = __floats2bfloat162_rn(a.x + b.x, a.y + b.y);
    cv.h.b = __floats2bfloat162_rn(a.z + b.z, a.w + b.w);
    ((uint2*)g_Wsh)[i] = cv.u;
}

// =====================================================================
// Kernel 2: 10 power iterations on bf16 Ws. One block/batch, 1024 threads.
// 8-way d-split, each thread 4 consecutive c via uint2 (4 bf16).
// =====================================================================
__global__ __launch_bounds__(1024)
void power_kernel(const float* __restrict__ vin) {
    const int b = blockIdx.x, t = threadIdx.x;
    const int h = t >> 7;        // d-chunk 0..7 (64 d each)
    const int cg = t & 127;      // c-group: c = 4*cg
    __shared__ float vs[NC];
    __shared__ float part[8 * NC];
    __shared__ float red[16];
    __shared__ float tot;

    const __nv_bfloat16* __restrict__ Wh = g_Wsh + (size_t)b * NC * NC;
    if (t < NC) vs[t] = vin[b * NC + t];
    __syncthreads();

    const uint2* __restrict__ base = (const uint2*)(Wh + (size_t)(h * 64) * NC) + cg;

    for (int it = 0; it < NIP; it++) {
        float a0 = 0.f, a1 = 0.f, a2 = 0.f, a3 = 0.f;
        #pragma unroll 16
        for (int d = 0; d < 64; d++) {
            const uint2 p = base[(size_t)d * (NC / 4)];
            const float vv = vs[h * 64 + d];
            a0 += vv * bflo(p.x); a1 += vv * bfhi(p.x);
            a2 += vv * bflo(p.y); a3 += vv * bfhi(p.y);
        }
        *(float4*)&part[h * NC + cg * 4] = make_float4(a0, a1, a2, a3);
        __syncthreads();

        float nv = 0.f;
        if (t < NC) {
            #pragma unroll
            for (int hh = 0; hh < 8; hh++) nv += part[hh * NC + t];
            float s = nv * nv;
            #pragma unroll
            for (int o = 16; o > 0; o >>= 1)
                s += __shfl_xor_sync(0xffffffffu, s, o);
            if ((t & 31) == 0) red[t >> 5] = s;
        }
        __syncthreads();
        if (t == 0) {
            float x = 0.f;
            #pragma unroll
            for (int i = 0; i < 16; i++) x += red[i];
            tot = x;
        }
        __syncthreads();
        if (t < NC) vs[t] = nv * rsqrtf(tot);
        __syncthreads();
    }
    if (t < NC) g_v[b * NC + t] = vs[t];
}

// =====================================================================
// Kernel 3: u partials from bf16 X. grid (4, 16, 16), 256 thr,
// each thread 4 n via uint2 (4 bf16), 32 c.
// =====================================================================
__global__ __launch_bounds__(256)
void u_part_kernel() {
    const int b = blockIdx.z, ch = blockIdx.y;
    const int n0 = blockIdx.x * 1024 + threadIdx.x * 4;
    __shared__ float vsh[32];
    if (threadIdx.x < 32) vsh[threadIdx.x] = g_v[b * NC + ch * 32 + threadIdx.x];
    __syncthreads();

    const __nv_bfloat16* __restrict__ Xp = g_xh + (size_t)b * NC * NHW + (size_t)(ch * 32) * NHW;
    float a0 = 0.f, a1 = 0.f, a2 = 0.f, a3 = 0.f;
    #pragma unroll
    for (int cc = 0; cc < 32; cc++) {
        const uint2 p = *(const uint2*)&Xp[(size_t)cc * NHW + n0];
        const float vv = vsh[cc];
        a0 += vv * bflo(p.x); a1 += vv * bfhi(p.x);
        a2 += vv * bflo(p.y); a3 += vv * bfhi(p.y);
    }
    *(float4*)&g_upar[(size_t)(b * 16 + ch) * NHW + n0] = make_float4(a0, a1, a2, a3);
}

// =====================================================================
// Kernel 4: reduce c-chunk partials -> g_u, compute 1/||u||. grid 16, 512 thr.
// =====================================================================
__global__ __launch_bounds__(512)
void u_reduce_kernel() {
    const int b = blockIdx.x, t = threadIdx.x;
    __shared__ float red[16];
    float sq = 0.f;
    #pragma unroll
    for (int j = 0; j < 8; j++) {
        const int n = j * 512 + t;
        float s = 0.f;
        #pragma unroll
        for (int ch = 0; ch < 16; ch++)
            s += g_upar[(size_t)(b * 16 + ch) * NHW + n];
        g_u[b * NHW + n] = s;
        sq += s * s;
    }
    #pragma unroll
    for (int o = 16; o > 0; o >>= 1)
        sq += __shfl_xor_sync(0xffffffffu, sq, o);
    if ((t & 31) == 0) red[t >> 5] = sq;
    __syncthreads();
    if (t == 0) {
        float x = 0.f;
        #pragma unroll
        for (int i = 0; i < 16; i++) x += red[i];
        g_uinv[b] = rsqrtf(x);
    }
}

// =====================================================================
// Kernel 5: out = x + (v * 1/||u||) outer u. float4 streaming (f32 x).
// =====================================================================
__global__ __launch_bounds__(256)
void final_kernel(const float* __restrict__ x, float* __restrict__ out) {
    const size_t i = (size_t)blockIdx.x * 256 + threadIdx.x;   // float4 idx
    const size_t e = i * 4;
    const int b   = (int)(e >> 21);                 // NC*NHW = 2^21
    const int rem = (int)(e & ((1u << 21) - 1));
    const int c   = rem >> 12;                      // NHW = 2^12
    const int n   = rem & (NHW - 1);
    const float vc = g_v[b * NC + c] * g_uinv[b];
    const float4 u4 = *(const float4*)&g_u[b * NHW + n];
    const float4 xv = *(const float4*)&x[e];
    float4 o;
    o.x = xv.x + vc * u4.x;
    o.y = xv.y + vc * u4.y;
    o.z = xv.z + vc * u4.z;
    o.w = xv.w + vc * u4.w;
    *(float4*)&out[e] = o;
}

// =====================================================================
extern "C" void kernel_launch(void* const* d_in, const int* in_sizes, int n_in,
                              void* d_out, int out_size) {
    const float* x  = (const float*)d_in[0];
    const float* v0 = (const float*)d_in[1];
    float* out = (float*)d_out;

    cudaFuncSetAttribute(gram_mma, cudaFuncAttributeMaxDynamicSharedMemorySize, GRAM_SMEM);

    conv_kernel<<<16384, 256>>>(x, 0);         // launch 1
    conv_kernel<<<16384, 256>>>(x, 16384*256); // launch 2
    prep_kernel<<<1, 32>>>();                  // launch 3 (slot filler)
    gram_mma<<<dim3(20, NB, 2), 256, GRAM_SMEM>>>();   // launch 4 <- ncu capture slot
    combine_kernel<<<4096, 256>>>();           // sum halves -> bf16 Ws
    power_kernel<<<NB, 1024>>>(v0);
    u_part_kernel<<<dim3(4, 16, NB), 256>>>();
    u_reduce_kernel<<<NB, 512>>>();
    final_kernel<<<32768, 256>>>(x, out);
}

// round 14
// speedup vs baseline: 1.2542x; 1.0377x over previous
#include <cuda_runtime.h>
#include <cuda_bf16.h>
#include <cstdint>

#define NB  16
#define NC  512
#define NHW 4096
#define NIP 10

// ---------------- scratch (static device globals; no allocations) ----------------
__device__ __align__(16) __nv_bfloat16 g_xh[NB*NC*NHW];    // bf16 copy of x (64MB)
__device__ __align__(16) __nv_bfloat16 g_WhA[NB*NC*NC];    // split-K half 0, bf16 (8MB)
__device__ __align__(16) __nv_bfloat16 g_WhB[NB*NC*NC];    // split-K half 1, bf16 (8MB)
__device__ __align__(16) __nv_bfloat16 g_Wsh[NB*NC*NC];    // Gram bf16 (8MB)
__device__ float g_v  [NB*NC];        // v after 10 power iterations
__device__ float g_u  [NB*NHW];       // unnormalized u = X^T v
__device__ float g_upar[NB*16*NHW];   // c-chunk partials of u (4MB)
__device__ float g_uinv [NB];         // 1/||u||

// ================= PTX helpers =================
__device__ __forceinline__ uint32_t smem_u32(const void* p) {
    uint32_t a;
    asm("{ .reg .u64 t; cvta.to.shared.u64 t, %1; cvt.u32.u64 %0, t; }" : "=r"(a) : "l"(p));
    return a;
}
__device__ __forceinline__ void cp16(uint32_t dst, const void* gsrc) {
    asm volatile("cp.async.cg.shared.global [%0], [%1], 16;"
                 :: "r"(dst), "l"(__cvta_generic_to_global(gsrc)) : "memory");
}
#define CP_COMMIT() asm volatile("cp.async.commit_group;" ::: "memory")

__device__ __forceinline__ void ldsm4(uint32_t* r, uint32_t addr) {
    asm volatile("ldmatrix.sync.aligned.m8n8.x4.shared.b16 {%0,%1,%2,%3}, [%4];"
        : "=r"(r[0]), "=r"(r[1]), "=r"(r[2]), "=r"(r[3]) : "r"(addr));
}
__device__ __forceinline__ void mma16816(float* d, const uint32_t* a, uint32_t b0, uint32_t b1) {
    asm volatile("mma.sync.aligned.m16n8k16.row.col.f32.bf16.bf16.f32 "
        "{%0,%1,%2,%3}, {%4,%5,%6,%7}, {%8,%9}, {%0,%1,%2,%3};"
        : "+f"(d[0]), "+f"(d[1]), "+f"(d[2]), "+f"(d[3])
        : "r"(a[0]), "r"(a[1]), "r"(a[2]), "r"(a[3]), "r"(b0), "r"(b1));
}
__device__ __forceinline__ float bflo(uint32_t p) { return __uint_as_float(p << 16); }
__device__ __forceinline__ float bfhi(uint32_t p) { return __uint_as_float(p & 0xffff0000u); }

// =====================================================================
// Kernel 0: convert x (f32) -> g_xh (bf16). Single launch.
// =====================================================================
__global__ __launch_bounds__(256)
void conv_kernel(const float* __restrict__ x) {
    const size_t i = (size_t)blockIdx.x * 256 + threadIdx.x;  // float4 idx
    const float4 v = ((const float4*)x)[i];
    union { struct { __nv_bfloat162 a, b; } h; uint2 u; } cv;
    cv.h.a = __floats2bfloat162_rn(v.x, v.y);
    cv.h.b = __floats2bfloat162_rn(v.z, v.w);
    ((uint2*)g_xh)[i] = cv.u;
}

// =====================================================================
// Kernel 1: Gram via bf16 mma.sync (R13-proven core). CTA tile 64x128,
// 256 thr = 8 warps (2m x 4n of 32x32), __launch_bounds__(256,3).
// Symmetric decomposition (mi in 0..7, nj in 0..3): tiles with mi >= 2nj.
// Straddle tiles alias A into B smem. Split-K=2, BK=32, 4-stage cp.async,
// prefetch +2, one barrier per chunk. Epilogue writes bf16 halves.
// =====================================================================
#define BK 32
#define A_BYTES (64 * 80)             // 5120
#define B_BYTES (128 * 80)            // 10240
#define STAGE_BYTES (A_BYTES + B_BYTES)  // 15360
#define GRAM_SMEM (4 * STAGE_BYTES)   // 61440 >= epilogue 64*129*4 (33024)

__global__ __launch_bounds__(256, 3)
void gram_mma(void) {
    extern __shared__ char ds[];
    const uint32_t sb = smem_u32(ds);
    const int tid = threadIdx.x;
    const int wid = tid >> 5, lane = tid & 31;

    const int b = blockIdx.y;
    const int z = blockIdx.z;            // split-K half
    int nj = 0, r = blockIdx.x;
    while (r >= 8 - 2 * nj) { r -= 8 - 2 * nj; nj++; }
    const int mi = 2 * nj + r;
    const int i0 = mi * 64, j0 = nj * 128;
    const bool straddle = (mi == 2 * nj) || (mi == 2 * nj + 1);
    const bool dotrans  = (mi >= 2 * nj + 2);
    const int kbase = z * 2048;

    const __nv_bfloat16* __restrict__ Xb = g_xh + (size_t)b * NC * NHW;
    __nv_bfloat16* __restrict__ Whz = (z ? g_WhB : g_WhA) + (size_t)b * NC * NC;

    // loader: B = 2 cp16/thread (128 rows x 4 qcols), A = 1 cp16/thread (64 x 4)
    const int br0 = tid >> 2,          bq0 = tid & 3;
    const int br1 = (tid + 256) >> 2,  bq1 = tid & 3;
    const int arow = tid >> 2,         akq = tid & 3;

    auto load_chunk = [&](int c) {
        const uint32_t stg = sb + (uint32_t)(c & 3) * STAGE_BYTES;
        const uint32_t bbs = stg + A_BYTES;
        const __nv_bfloat16* gB = Xb + (size_t)j0 * NHW + kbase + c * BK;
        cp16(bbs + br0 * 80 + bq0 * 16, gB + (size_t)br0 * NHW + bq0 * 8);
        cp16(bbs + br1 * 80 + bq1 * 16, gB + (size_t)br1 * NHW + bq1 * 8);
        if (!straddle) {
            const __nv_bfloat16* gA = Xb + (size_t)i0 * NHW + kbase + c * BK;
            cp16(stg + arow * 80 + akq * 16, gA + (size_t)arow * NHW + akq * 8);
        }
        CP_COMMIT();
    };

    load_chunk(0); load_chunk(1);

    // per-lane ldmatrix address offsets (bytes) — verified R5..R13
    const uint32_t aoff = (uint32_t)((lane & 15) * 80 + (lane >> 4) * 16);
    const uint32_t boff = (uint32_t)(((lane & 7) | (((lane >> 4) & 1) << 3)) * 80
                                     + ((lane >> 3) & 1) * 16);
    const uint32_t wmB = (uint32_t)((wid & 1) * 32) * 80;   // warp m0 byte off
    const uint32_t wnB = (uint32_t)((wid >> 1) * 32) * 80;  // warp n0 byte off
    const uint32_t astrad = (uint32_t)(mi & 1) * 5120u;     // A offset inside B tile

    float acc[2][4][4];
    #pragma unroll
    for (int mt = 0; mt < 2; mt++)
        #pragma unroll
        for (int nt = 0; nt < 4; nt++)
            #pragma unroll
            for (int q = 0; q < 4; q++) acc[mt][nt][q] = 0.f;

    for (int c = 0; c < 64; c++) {
        if (c < 63) asm volatile("cp.async.wait_group 1;" ::: "memory");
        else        asm volatile("cp.async.wait_group 0;" ::: "memory");
        __syncthreads();     // chunk c resident; stage (c+2)%4 reads (chunk c-2) done

        if (c + 2 < 64) load_chunk(c + 2);

        const uint32_t stg = sb + (uint32_t)(c & 3) * STAGE_BYTES;
        const uint32_t bbs = stg + A_BYTES;
        const uint32_t abs_ = straddle ? (bbs + astrad) : stg;

        #pragma unroll
        for (int ks = 0; ks < 2; ks++) {
            uint32_t af[2][4], bf[2][4];
            #pragma unroll
            for (int mt = 0; mt < 2; mt++)
                ldsm4(af[mt], abs_ + wmB + (uint32_t)(mt * 1280 + ks * 32) + aoff);
            #pragma unroll
            for (int nh = 0; nh < 2; nh++)
                ldsm4(bf[nh], bbs + wnB + (uint32_t)(nh * 1280 + ks * 32) + boff);
            #pragma unroll
            for (int mt = 0; mt < 2; mt++)
                #pragma unroll
                for (int nt = 0; nt < 4; nt++)
                    mma16816(acc[mt][nt], af[mt], bf[nt >> 1][2 * (nt & 1)],
                             bf[nt >> 1][2 * (nt & 1) + 1]);
        }
    }
    __syncthreads();   // all MMA reads done before smem reuse

    // ---- epilogue: stage 64x128 C in smem (stride 129 floats) ----
    float* st = (float*)ds;
    {
        const int gid = lane >> 2, tig = lane & 3;
        const int wm0 = (wid & 1) * 32, wn0 = (wid >> 1) * 32;
        #pragma unroll
        for (int mt = 0; mt < 2; mt++)
            #pragma unroll
            for (int nt = 0; nt < 4; nt++) {
                const int m = wm0 + mt * 16 + gid;
                const int n = wn0 + nt * 8 + tig * 2;
                st[m * 129 + n]           = acc[mt][nt][0];
                st[m * 129 + n + 1]       = acc[mt][nt][1];
                st[(m + 8) * 129 + n]     = acc[mt][nt][2];
                st[(m + 8) * 129 + n + 1] = acc[mt][nt][3];
            }
    }
    __syncthreads();

    // direct block (i0, j0): 64 x 128, bf16
    #pragma unroll
    for (int it = 0; it < 8; it++) {
        const int e = it * 256 + tid;        // 2048 uint2 (4 cols each)
        const int row = e >> 5, n = (e & 31) * 4;
        union { struct { __nv_bfloat162 a, b; } h; uint2 u; } cv;
        cv.h.a = __floats2bfloat162_rn(st[row * 129 + n],     st[row * 129 + n + 1]);
        cv.h.b = __floats2bfloat162_rn(st[row * 129 + n + 2], st[row * 129 + n + 3]);
        *(uint2*)&Whz[(size_t)(i0 + row) * NC + j0 + n] = cv.u;
    }
    // transposed block (j0, i0): 128 x 64, bf16
    if (dotrans) {
        #pragma unroll
        for (int it = 0; it < 8; it++) {
            const int e = it * 256 + tid;    // 2048 uint2
            const int n = e >> 4, m = (e & 15) * 4;
            union { struct { __nv_bfloat162 a, b; } h; uint2 u; } cv;
            cv.h.a = __floats2bfloat162_rn(st[m * 129 + n],       st[(m + 1) * 129 + n]);
            cv.h.b = __floats2bfloat162_rn(st[(m + 2) * 129 + n], st[(m + 3) * 129 + n]);
            *(uint2*)&Whz[(size_t)(j0 + n) * NC + i0 + m] = cv.u;
        }
    }
}

// =====================================================================
// Kernel 1b: combine bf16 split-K halves -> g_Wsh. Full-chip, uint4.
// =====================================================================
__global__ __launch_bounds__(256)
void combine_kernel() {
    const size_t i = (size_t)blockIdx.x * 256 + threadIdx.x;   // uint4 idx (4M/8)
    const uint4 a = ((const uint4*)g_WhA)[i];
    const uint4 b = ((const uint4*)g_WhB)[i];
    uint4 o;
    const __nv_bfloat162* pa = (const __nv_bfloat162*)&a;
    const __nv_bfloat162* pb = (const __nv_bfloat162*)&b;
    __nv_bfloat162* po = (__nv_bfloat162*)&o;
    #pragma unroll
    for (int k = 0; k < 4; k++) po[k] = __hadd2(pa[k], pb[k]);
    ((uint4*)g_Wsh)[i] = o;
}

// =====================================================================
// Kernel 2: 10 power iterations on bf16 Ws. One block/batch, 1024 threads.
// 8-way d-split, each thread 4 consecutive c via uint2 (4 bf16).
// <- ncu capture slot this round.
// =====================================================================
__global__ __launch_bounds__(1024)
void power_kernel(const float* __restrict__ vin) {
    const int b = blockIdx.x, t = threadIdx.x;
    const int h = t >> 7;        // d-chunk 0..7 (64 d each)
    const int cg = t & 127;      // c-group: c = 4*cg
    __shared__ float vs[NC];
    __shared__ float part[8 * NC];
    __shared__ float red[16];
    __shared__ float tot;

    const __nv_bfloat16* __restrict__ Wh = g_Wsh + (size_t)b * NC * NC;
    if (t < NC) vs[t] = vin[b * NC + t];
    __syncthreads();

    const uint2* __restrict__ base = (const uint2*)(Wh + (size_t)(h * 64) * NC) + cg;

    for (int it = 0; it < NIP; it++) {
        float a0 = 0.f, a1 = 0.f, a2 = 0.f, a3 = 0.f;
        #pragma unroll 16
        for (int d = 0; d < 64; d++) {
            const uint2 p = base[(size_t)d * (NC / 4)];
            const float vv = vs[h * 64 + d];
            a0 += vv * bflo(p.x); a1 += vv * bfhi(p.x);
            a2 += vv * bflo(p.y); a3 += vv * bfhi(p.y);
        }
        *(float4*)&part[h * NC + cg * 4] = make_float4(a0, a1, a2, a3);
        __syncthreads();

        float nv = 0.f;
        if (t < NC) {
            #pragma unroll
            for (int hh = 0; hh < 8; hh++) nv += part[hh * NC + t];
            float s = nv * nv;
            #pragma unroll
            for (int o = 16; o > 0; o >>= 1)
                s += __shfl_xor_sync(0xffffffffu, s, o);
            if ((t & 31) == 0) red[t >> 5] = s;
        }
        __syncthreads();
        if (t == 0) {
            float x = 0.f;
            #pragma unroll
            for (int i = 0; i < 16; i++) x += red[i];
            tot = x;
        }
        __syncthreads();
        if (t < NC) vs[t] = nv * rsqrtf(tot);
        __syncthreads();
    }
    if (t < NC) g_v[b * NC + t] = vs[t];
}

// =====================================================================
// Kernel 3: u partials from bf16 X. grid (4, 16, 16), 256 thr,
// each thread 4 n via uint2 (4 bf16), 32 c.
// =====================================================================
__global__ __launch_bounds__(256)
void u_part_kernel() {
    const int b = blockIdx.z, ch = blockIdx.y;
    const int n0 = blockIdx.x * 1024 + threadIdx.x * 4;
    __shared__ float vsh[32];
    if (threadIdx.x < 32) vsh[threadIdx.x] = g_v[b * NC + ch * 32 + threadIdx.x];
    __syncthreads();

    const __nv_bfloat16* __restrict__ Xp = g_xh + (size_t)b * NC * NHW + (size_t)(ch * 32) * NHW;
    float a0 = 0.f, a1 = 0.f, a2 = 0.f, a3 = 0.f;
    #pragma unroll
    for (int cc = 0; cc < 32; cc++) {
        const uint2 p = *(const uint2*)&Xp[(size_t)cc * NHW + n0];
        const float vv = vsh[cc];
        a0 += vv * bflo(p.x); a1 += vv * bfhi(p.x);
        a2 += vv * bflo(p.y); a3 += vv * bfhi(p.y);
    }
    *(float4*)&g_upar[(size_t)(b * 16 + ch) * NHW + n0] = make_float4(a0, a1, a2, a3);
}

// =====================================================================
// Kernel 4: reduce c-chunk partials -> g_u, compute 1/||u||. grid 16, 512 thr.
// =====================================================================
__global__ __launch_bounds__(512)
void u_reduce_kernel() {
    const int b = blockIdx.x, t = threadIdx.x;
    __shared__ float red[16];
    float sq = 0.f;
    #pragma unroll
    for (int j = 0; j < 8; j++) {
        const int n = j * 512 + t;
        float s = 0.f;
        #pragma unroll
        for (int ch = 0; ch < 16; ch++)
            s += g_upar[(size_t)(b * 16 + ch) * NHW + n];
        g_u[b * NHW + n] = s;
        sq += s * s;
    }
    #pragma unroll
    for (int o = 16; o > 0; o >>= 1)
        sq += __shfl_xor_sync(0xffffffffu, sq, o);
    if ((t & 31) == 0) red[t >> 5] = sq;
    __syncthreads();
    if (t == 0) {
        float x = 0.f;
        #pragma unroll
        for (int i = 0; i < 16; i++) x += red[i];
        g_uinv[b] = rsqrtf(x);
    }
}

// =====================================================================
// Kernel 5: out = x + (v * 1/||u||) outer u. float4 streaming (f32 x).
// =====================================================================
__global__ __launch_bounds__(256)
void final_kernel(const float* __restrict__ x, float* __restrict__ out) {
    const size_t i = (size_t)blockIdx.x * 256 + threadIdx.x;   // float4 idx
    const size_t e = i * 4;
    const int b   = (int)(e >> 21);                 // NC*NHW = 2^21
    const int rem = (int)(e & ((1u << 21) - 1));
    const int c   = rem >> 12;                      // NHW = 2^12
    const int n   = rem & (NHW - 1);
    const float vc = g_v[b * NC + c] * g_uinv[b];
    const float4 u4 = *(const float4*)&g_u[b * NHW + n];
    const float4 xv = *(const float4*)&x[e];
    float4 o;
    o.x = xv.x + vc * u4.x;
    o.y = xv.y + vc * u4.y;
    o.z = xv.z + vc * u4.z;
    o.w = xv.w + vc * u4.w;
    *(float4*)&out[e] = o;
}

// =====================================================================
extern "C" void kernel_launch(void* const* d_in, const int* in_sizes, int n_in,
                              void* d_out, int out_size) {
    const float* x  = (const float*)d_in[0];
    const float* v0 = (const float*)d_in[1];
    float* out = (float*)d_out;

    cudaFuncSetAttribute(gram_mma, cudaFuncAttributeMaxDynamicSharedMemorySize, GRAM_SMEM);

    conv_kernel<<<32768, 256>>>(x);                    // launch 1
    gram_mma<<<dim3(20, NB, 2), 256, GRAM_SMEM>>>();   // launch 2
    combine_kernel<<<2048, 256>>>();                   // launch 3
    power_kernel<<<NB, 1024>>>(v0);                    // launch 4 <- ncu capture slot
    u_part_kernel<<<dim3(4, 16, NB), 256>>>();
    u_reduce_kernel<<<NB, 512>>>();
    final_kernel<<<32768, 256>>>(x, out);
}